// round 13
// baseline (speedup 1.0000x reference)
#include <cuda_runtime.h>
#include <cstdint>

// WholeMask R13 (= R11/R12 resubmit; broker container failures x2, same
// pipeline pattern ran fine in R9/R10): CE-memset zero-fill + near-zero-
// overhead box painter.
// Evidence: CE memset streams 134MB @ ~6.7TB/s (~20us), faster than any SM
// store loop measured (~5.5TB/s ceiling, R1-R7). R10 showed paint cost was
// per-CTA setup, so strip it: bbox LDG.128 + count only; masks gathered via
// __ldg (401KB, L2-resident); divisions only for painted pixels.

#define MH 28
#define MW 28
#define IMG 512

__global__ __launch_bounds__(128, 12)
void box_paint_kernel(const float* __restrict__ bboxess,
                      const int*   __restrict__ counts,
                      const float* __restrict__ maskss,
                      float*       __restrict__ out,
                      int Kk)
{
    const int slice = blockIdx.x;              // b*K + k
    const int b = slice / Kk;
    const int k = slice - b * Kk;

    if (k >= __ldg(counts + b)) return;        // block-uniform exit

    // Rounded (half-even == jnp.round) + clipped box.
    const float4 bb = __ldg(reinterpret_cast<const float4*>(bboxess) + slice);
    int y1 = __float2int_rn(bb.x);
    int x1 = __float2int_rn(bb.y);
    int y2 = __float2int_rn(bb.z);
    int x2 = __float2int_rn(bb.w);
    y1 = min(max(y1, 0), IMG - 1);
    x1 = min(max(x1, 0), IMG - 1);
    y2 = min(max(y2, y1 + 1), IMG);
    x2 = min(max(x2, x1 + 1), IMG);
    const int h = y2 - y1;
    const int w = x2 - x1;

    const int lane = threadIdx.x & 31;
    const int wrp  = threadIdx.x >> 5;         // 0..3
    const int g    = blockIdx.y * 4 + wrp;     // warp id 0..31 per slice
    const int xa   = x1 & ~3;                  // aligned span start

    const float* gm = maskss + (size_t)slice * (MH * MW);
    float* obase = out + (size_t)slice * (IMG * IMG);

    // Rows r = g, g+32, ... inside the box (h <= ~150 -> <=5 iterations).
    for (int r = g; r < h; r += 32) {
        const int y = y1 + r;
        int sy = r * MH / h;                   // warp-uniform
        sy = min(sy, MH - 1);
        const float* mrow = gm + sy * MW;
        float* orow = obase + (size_t)y * IMG;

        // Lanes cover the x-span in float4 quads (w <= ~150 -> <=2 iters).
        for (int xq = xa + lane * 4; xq < x2; xq += 128) {
            float4 v;
            #pragma unroll
            for (int c = 0; c < 4; ++c) {
                const int x = xq + c;
                float val = 0.f;
                if (x >= x1 && x < x2) {
                    int sx = (x - x1) * MW / w;
                    sx = min(sx, MW - 1);
                    val = __ldg(mrow + sx);    // L2-resident gather
                }
                (&v.x)[c] = val;
            }
            *reinterpret_cast<float4*>(orow + xq) = v;  // zeros over zeros OK
        }
    }
}

extern "C" void kernel_launch(void* const* d_in, const int* in_sizes, int n_in,
                              void* d_out, int out_size)
{
    const float* bboxess = (const float*)d_in[0];   // (B,K,4) f32
    const int*   counts  = (const int*)  d_in[1];   // (B,1)   i32
    const float* maskss  = (const float*)d_in[2];   // (B,K,1,28,28) f32

    const int BK = in_sizes[0] / 4;                 // B*K
    const int Bv = in_sizes[1];                     // B
    const int Kk = BK / Bv;                         // K

    // Bulk zero-fill via driver/CE memset (graph memset node, ~6.7 TB/s).
    cudaMemsetAsync(d_out, 0, (size_t)out_size * sizeof(float), 0);

    // Paint only box interiors (~2-3 MB).
    dim3 block(128);
    dim3 grid(BK, 8);              // 1024 CTAs, 4096 warps, one wave
    box_paint_kernel<<<grid, block>>>(bboxess, counts, maskss,
                                      (float*)d_out, Kk);
}

// round 16
// speedup vs baseline: 1.1060x; 1.1060x over previous
#include <cuda_runtime.h>
#include <cstdint>

// WholeMask R16 (same theory as R14/R15, reshaped launch after two broker
// failures): CE-memset zero-fill + one-row-per-warp painter.
// R13 diagnosis: paint latency-bound (occ 21%, L2 3%) — few surviving warps
// serializing load->div->gather->store chains. Fix: ~19.4K warps, one box
// row each, magic-multiply (umulhi) division instead of per-pixel int div.

#define MH 28
#define MW 28
#define IMG 512
#define ROWS_PER_SLICE 152        // >= max box height in data; looped anyway

__global__ __launch_bounds__(256, 8)
void box_paint_kernel(const float* __restrict__ bboxess,
                      const int*   __restrict__ counts,
                      const float* __restrict__ maskss,
                      float*       __restrict__ out,
                      int Kk)
{
    const int slice = blockIdx.x;              // b*K + k
    const int b = slice / Kk;
    const int k = slice - b * Kk;

    if (k >= __ldg(counts + b)) return;        // block-uniform exit

    // Rounded (half-even == jnp.round) + clipped box.
    const float4 bb = __ldg(reinterpret_cast<const float4*>(bboxess) + slice);
    int y1 = __float2int_rn(bb.x);
    int x1 = __float2int_rn(bb.y);
    int y2 = __float2int_rn(bb.z);
    int x2 = __float2int_rn(bb.w);
    y1 = min(max(y1, 0), IMG - 1);
    x1 = min(max(x1, 0), IMG - 1);
    y2 = min(max(y2, y1 + 1), IMG);
    x2 = min(max(x2, x1 + 1), IMG);
    const int h = y2 - y1;
    const int w = x2 - x1;

    const int lane = threadIdx.x & 31;
    const int wrp  = threadIdx.x >> 5;         // 0..7
    const int r0   = blockIdx.y * 8 + wrp;     // this warp's first box row

    if (r0 >= h) return;                       // warp-uniform

    // Exact floor-division magics: q = umulhi(a, m) == a / d
    // for m = ceil(2^32/d) = 0xFFFFFFFF/d + 1, valid while a*d < 2^32.
    const unsigned mh_magic = 0xFFFFFFFFu / (unsigned)h + 1;
    const unsigned mw_magic = 0xFFFFFFFFu / (unsigned)w + 1;

    const int xa = x1 & ~3;                    // aligned span start
    const float* gm = maskss + (size_t)slice * (MH * MW);
    float* obase = out + (size_t)slice * (IMG * IMG);

    // Normally exactly one iteration (h <= 152); loop keeps it general.
    for (int r = r0; r < h; r += ROWS_PER_SLICE) {
        int sy = (int)__umulhi((unsigned)(r * MH), mh_magic);
        sy = min(sy, MH - 1);
        const float* mrow = gm + sy * MW;
        float* orow = obase + (size_t)(y1 + r) * IMG;

        // Lanes cover the x-span in float4 quads (w <= ~152 -> <= 2 iters).
        for (int xq = xa + lane * 4; xq < x2; xq += 128) {
            float4 v;
            #pragma unroll
            for (int c = 0; c < 4; ++c) {
                const int x = xq + c;
                float val = 0.f;
                if (x >= x1 && x < x2) {
                    int sx = (int)__umulhi((unsigned)((x - x1) * MW), mw_magic);
                    sx = min(sx, MW - 1);
                    val = __ldg(mrow + sx);    // L2-resident gather
                }
                (&v.x)[c] = val;
            }
            *reinterpret_cast<float4*>(orow + xq) = v;  // zeros over zeros OK
        }
    }
}

extern "C" void kernel_launch(void* const* d_in, const int* in_sizes, int n_in,
                              void* d_out, int out_size)
{
    const float* bboxess = (const float*)d_in[0];   // (B,K,4) f32
    const int*   counts  = (const int*)  d_in[1];   // (B,1)   i32
    const float* maskss  = (const float*)d_in[2];   // (B,K,1,28,28) f32

    const int BK = in_sizes[0] / 4;                 // B*K
    const int Bv = in_sizes[1];                     // B
    const int Kk = BK / Bv;                         // K

    // Bulk zero-fill via driver/CE memset (graph memset node, ~6.7 TB/s).
    cudaMemsetAsync(d_out, 0, (size_t)out_size * sizeof(float), 0);

    // Paint box interiors: one row per warp.
    dim3 block(256);
    dim3 grid(BK, (ROWS_PER_SLICE + 7) / 8);   // 128 x 19 CTAs = 19456 warps
    box_paint_kernel<<<grid, block>>>(bboxess, counts, maskss,
                                      (float*)d_out, Kk);
}